// round 10
// baseline (speedup 1.0000x reference)
#include <cuda_runtime.h>

// ---------------------------------------------------------------------------
// SSIM (5x5 Gaussian, sigma=1.5, SAME zero padding), fused single kernel.
// R10: smem-free, sync-free. Warp-shuffle horizontal pass:
//      lane owns 1 column; (s,d)=(a+b,a-b) scalars shuffled to neighbors
//      (8 shfl/ch; neighbor squares recomputed locally). Warp covers 32
//      cols, outputs middle 28 (edge lanes give exact zero padding at the
//      image borders). Register rolling ring + vertical pass as in R8.
//      Removes: syncwarp x2/step, 5 STS/step, 15 LDS/step, 18 halo LDGs.
// ---------------------------------------------------------------------------

constexpr int W     = 512;
constexpr int H     = 512;
constexpr int C     = 3;
constexpr int NB    = 16;
constexpr int ROWS  = 32;           // output rows per block
constexpr int STEPS = ROWS + 4;     // 36 input rows
constexpr int OUTW  = 28;           // output cols per warp (lanes 2..29)
constexpr int WPB   = 4;            // warps per block
constexpr int GRIDX = (W + OUTW * WPB - 1) / (OUTW * WPB);   // 5

typedef unsigned long long u64;

__device__ __forceinline__ u64 pk2(float lo, float hi) {
    u64 r;
    asm("mov.b64 %0, {%1, %2};" : "=l"(r) : "f"(lo), "f"(hi));
    return r;
}
__device__ __forceinline__ void up2(u64 v, float& lo, float& hi) {
    asm("mov.b64 {%0, %1}, %2;" : "=f"(lo), "=f"(hi) : "l"(v));
}
__device__ __forceinline__ u64 fma2_(u64 a, u64 b, u64 c) {
    u64 d;
    asm("fma.rn.f32x2 %0, %1, %2, %3;" : "=l"(d) : "l"(a), "l"(b), "l"(c));
    return d;
}

__global__ __launch_bounds__(128, 4)
void ssim_kernel(const float* __restrict__ img1,
                 const float* __restrict__ img2,
                 const float* __restrict__ win,
                 float* __restrict__ out)
{
    const int lane = threadIdx.x & 31;
    const int warp = threadIdx.x >> 5;
    const int b    = blockIdx.z;
    const int y0   = blockIdx.y * ROWS;
    const int ws   = blockIdx.x * WPB + warp;     // warp strip id
    const int col  = ws * OUTW - 2 + lane;        // this lane's input column
    const bool colok = (col >= 0) && (col < W);
    const bool outok = (lane >= 2) && (lane < 30) && (col < W);

    // Separable 1D Gaussian: g[j] = w2d[2][j] / sqrt(w2d[2][2]).
    // Symmetric by construction: g[0]==g[4], g[1]==g[3] (bitwise).
    const float gc = sqrtf(win[12]);
    const float g0 = __fdividef(win[10], gc);
    const float g1 = __fdividef(win[11], gc);
    const float g2 = __fdividef(win[12], gc);
    u64 wg[5];
#pragma unroll
    for (int j = 0; j < 5; ++j) {
        const float gj = __fdividef(win[10 + j], gc);
        wg[j] = pk2(gj, gj);
    }

    int cbase[C];
#pragma unroll
    for (int c = 0; c < C; ++c) cbase[c] = ((b * C + c) * H) * W;

    // Rolling horizontal-filtered state: 5 row slots per channel (packed).
    u64 hSD[C][5], hSQ[C][5];

    // One-row-ahead prefetch registers (raw a, b per channel).
    float pa[C], pb[C];

    auto loadrow = [&](int r) {
        const bool rok = ((unsigned)r < (unsigned)H);
        const int rr = (rok ? r : 0) * W;
        float ta[C], tb[C];
#pragma unroll
        for (int c = 0; c < C; ++c) {
            ta[c] = colok ? img1[cbase[c] + rr + col] : 0.0f;
            tb[c] = colok ? img2[cbase[c] + rr + col] : 0.0f;
        }
#pragma unroll
        for (int c = 0; c < C; ++c) {
            pa[c] = rok ? ta[c] : 0.0f;
            pb[c] = rok ? tb[c] : 0.0f;
        }
    };

    loadrow(y0 - 2);

    const float C1 = 0.0001f;  // (0.01)^2
    const float C2 = 0.0009f;  // (0.03)^2

    for (int base = 0; base < STEPS; base += 5) {
#pragma unroll
        for (int k = 0; k < 5; ++k) {
            const int s = base + k;
            if (s < STEPS) {
                // ---- consume prefetched row: (s,d) per channel ----
                float sv[C], dv[C];
#pragma unroll
                for (int c = 0; c < C; ++c) {
                    sv[c] = pa[c] + pb[c];
                    dv[c] = pa[c] - pb[c];
                }

                // ---- prefetch next row (hidden behind shuffles/compute) ----
                loadrow(y0 - 1 + s);

                // ---- horizontal 5-tap via warp shuffles (no smem) ----
#pragma unroll
                for (int c = 0; c < C; ++c) {
                    const float s_ = sv[c], d_ = dv[c];
                    const float su1 = __shfl_up_sync(0xFFFFFFFFu, s_, 1);
                    const float su2 = __shfl_up_sync(0xFFFFFFFFu, s_, 2);
                    const float sn1 = __shfl_down_sync(0xFFFFFFFFu, s_, 1);
                    const float sn2 = __shfl_down_sync(0xFFFFFFFFu, s_, 2);
                    const float du1 = __shfl_up_sync(0xFFFFFFFFu, d_, 1);
                    const float du2 = __shfl_up_sync(0xFFFFFFFFu, d_, 2);
                    const float dn1 = __shfl_down_sync(0xFFFFFFFFu, d_, 1);
                    const float dn2 = __shfl_down_sync(0xFFFFFFFFu, d_, 2);
                    // symmetric combine: g2*v + g1*(v-1 + v+1) + g0*(v-2 + v+2)
                    float hs = g2 * s_;
                    hs = fmaf(g1, su1 + sn1, hs);
                    hs = fmaf(g0, su2 + sn2, hs);
                    float hd = g2 * d_;
                    hd = fmaf(g1, du1 + dn1, hd);
                    hd = fmaf(g0, du2 + dn2, hd);
                    float hs2 = g2 * (s_ * s_);
                    hs2 = fmaf(g1, fmaf(su1, su1, sn1 * sn1), hs2);
                    hs2 = fmaf(g0, fmaf(su2, su2, sn2 * sn2), hs2);
                    float hd2 = g2 * (d_ * d_);
                    hd2 = fmaf(g1, fmaf(du1, du1, dn1 * dn1), hd2);
                    hd2 = fmaf(g0, fmaf(du2, du2, dn2 * dn2), hd2);
                    hSD[c][s % 5] = pk2(hs, hd);
                    hSQ[c][s % 5] = pk2(hs2, hd2);
                }

                // ---- vertical 5-tap + epilogue for output row y0+s-4 ----
                if (s >= 4) {
                    float num[C], den[C];
#pragma unroll
                    for (int c = 0; c < C; ++c) {
                        u64 vsd = 0ull, vsq = 0ull;
#pragma unroll
                        for (int j = 0; j < 5; ++j) {
                            const int slot = (s + 1 + j) % 5;  // row s-4+j
                            vsd = fma2_(hSD[c][slot], wg[j], vsd);
                            vsq = fma2_(hSQ[c][slot], wg[j], vsq);
                        }
                        float cs, cd, css, csd;
                        up2(vsd, cs, cd);     // conv(s), conv(d)
                        up2(vsq, css, csd);   // conv(s^2), conv(d^2)
                        const float cs2 = cs * cs, cd2 = cd * cd;
                        const float m12 = (cs2 - cd2) * 0.25f;   // mu1*mu2
                        const float msq = (cs2 + cd2) * 0.5f;    // mu1^2+mu2^2
                        const float cab = (css - csd) * 0.25f;   // conv(ab)
                        const float csum = (css + csd) * 0.5f;   // conv(a2+b2)
                        const float s12  = cab - m12;            // sigma12
                        const float svar = csum - msq;           // var1+var2
                        num[c] = (2.0f * m12 + C1) * (2.0f * s12 + C2);
                        den[c] = (msq + C1) * (svar + C2);
                    }
                    // Sum of 3 ratios with a single division.
                    const float d01   = den[0] * den[1];
                    const float denom = d01 * den[2];
                    float numer = num[2] * d01;
                    numer = fmaf(num[0], den[1] * den[2], numer);
                    numer = fmaf(num[1], den[0] * den[2], numer);
                    if (outok) {
                        const int y = y0 + s - 4;
                        out[(b * H + y) * W + col] =
                            __fdividef(numer, denom) * (1.0f / 3.0f);
                    }
                }
            }
        }
    }
}

extern "C" void kernel_launch(void* const* d_in, const int* in_sizes, int n_in,
                              void* d_out, int out_size)
{
    const float* img1 = (const float*)d_in[0];
    const float* img2 = (const float*)d_in[1];
    const float* win  = (const float*)d_in[2];
    float* out = (float*)d_out;

    dim3 grid(GRIDX, H / ROWS, NB);  // (5, 16, 16) = 1280 blocks
    ssim_kernel<<<grid, 128>>>(img1, img2, win, out);
}

// round 11
// speedup vs baseline: 2.2368x; 2.2368x over previous
#include <cuda_runtime.h>

// ---------------------------------------------------------------------------
// SSIM (5x5 Gaussian, sigma=1.5, SAME zero padding), fused single kernel.
// R11 = R6 skeleton (per-warp smem staging, (s,d) transform, 1-row prefetch)
//       minus all per-step bounds overhead:
//   - columns: producers load from CLAMPED addresses unconditionally; each
//     consumer lane folds its per-tap validity into pre-masked horizontal
//     weights wgm[] (computed once). No per-step column SEL/SETP at all.
//   - rows: peeled. Steps 0,1 / 34,35 use checked loads; the 32 steady
//     steps use unchecked loads (interior rows are always valid).
// ---------------------------------------------------------------------------

constexpr int W    = 512;
constexpr int H    = 512;
constexpr int C    = 3;
constexpr int NB   = 16;
constexpr int BX   = 128;   // output columns per block (4 warps x 32)
constexpr int ROWS = 32;    // output rows per block

typedef unsigned long long u64;

__device__ __forceinline__ u64 pk2(float lo, float hi) {
    u64 r;
    asm("mov.b64 %0, {%1, %2};" : "=l"(r) : "f"(lo), "f"(hi));
    return r;
}
__device__ __forceinline__ void up2(u64 v, float& lo, float& hi) {
    asm("mov.b64 {%0, %1}, %2;" : "=f"(lo), "=f"(hi) : "l"(v));
}
__device__ __forceinline__ u64 fma2_(u64 a, u64 b, u64 c) {
    u64 d;
    asm("fma.rn.f32x2 %0, %1, %2, %3;" : "=l"(d) : "l"(a), "l"(b), "l"(c));
    return d;
}
__device__ __forceinline__ u64 mul2_(u64 a, u64 b) {
    u64 d;
    asm("mul.rn.f32x2 %0, %1, %2;" : "=l"(d) : "l"(a), "l"(b));
    return d;
}

__global__ __launch_bounds__(128, 4)
void ssim_kernel(const float* __restrict__ img1,
                 const float* __restrict__ img2,
                 const float* __restrict__ win,
                 float* __restrict__ out)
{
    // Per-warp row buffer (36 cols = 32 + 4 halo): (s,d) pairs.
    __shared__ float2 sSD[4][C][36];

    const int lane = threadIdx.x & 31;
    const int warp = threadIdx.x >> 5;
    const int b    = blockIdx.z;
    const int y0   = blockIdx.y * ROWS;
    const int x0   = blockIdx.x * BX + warp * 32;
    const int xo   = x0 + lane;           // output col (always < W)
    const int gx   = x0 - 2 + lane;       // main load col (may be < 0)
    const int gx2  = x0 + 30 + lane;      // halo load col (may be >= W)

    // Clamped load columns (garbage values masked by consumer weights).
    const int gxc  = gx < 0 ? 0 : gx;           // gx <= 509 always
    const int gx2c = gx2 > (W - 1) ? (W - 1) : gx2;  // gx2 >= 30 always

    // Separable 1D Gaussian: g[j] = w2d[2][j] / sqrt(w2d[2][2]).
    const float gc = sqrtf(win[12]);
    u64 wg[5];    // vertical weights (unmasked)
    u64 wgm[5];   // horizontal weights, masked by this lane's tap validity
#pragma unroll
    for (int j = 0; j < 5; ++j) {
        const float gj = __fdividef(win[10 + j], gc);
        wg[j] = pk2(gj, gj);
        const int tapcol = xo - 2 + j;
        const float mj = (tapcol >= 0 && tapcol < W) ? gj : 0.0f;
        wgm[j] = pk2(mj, mj);
    }

    int cb[C];
#pragma unroll
    for (int c = 0; c < C; ++c) cb[c] = ((b * C + c) * H) * W;

    // Rolling horizontal-filtered state: 5 row slots per channel (packed).
    u64 hSD[C][5], hSQ[C][5];

    // One-row-ahead prefetch registers (raw a, b; main + halo).
    float pa[C], pb[C], qa[C], qb[C];

    // Unchecked row load (rows known valid; cols clamped, masked downstream).
    auto loadrow_u = [&](int r) {
        const int rr = r * W;
#pragma unroll
        for (int c = 0; c < C; ++c) {
            const int o = cb[c] + rr;
            pa[c] = img1[o + gxc];
            pb[c] = img2[o + gxc];
            qa[c] = img1[o + gx2c];
            qb[c] = img2[o + gx2c];
        }
    };
    // Checked row load (top/bottom steps only).
    auto loadrow_c = [&](int r) {
        const bool rok = (r >= 0) && (r < H);
        const int rr = (rok ? r : 0) * W;
        float ta[C], tb[C], ua[C], ub[C];
#pragma unroll
        for (int c = 0; c < C; ++c) {
            const int o = cb[c] + rr;
            ta[c] = img1[o + gxc];
            tb[c] = img2[o + gxc];
            ua[c] = img1[o + gx2c];
            ub[c] = img2[o + gx2c];
        }
#pragma unroll
        for (int c = 0; c < C; ++c) {
            pa[c] = rok ? ta[c] : 0.0f;
            pb[c] = rok ? tb[c] : 0.0f;
            qa[c] = rok ? ua[c] : 0.0f;
            qb[c] = rok ? ub[c] : 0.0f;
        }
    };

    const float C1 = 0.0001f;  // (0.01)^2
    const float C2 = 0.0009f;  // (0.03)^2

    // One pipeline step. s: runtime step id (uniform). S5: compile-time
    // slot id (s % 5) so the ring stays in registers. prefetch: loads the
    // row for step s+1 (hidden behind this step's compute).
    auto step = [&](int s, int S5, auto&& prefetch) {
        // ---- store prefetched row s to smem as (s,d) ----
        __syncwarp();
#pragma unroll
        for (int c = 0; c < C; ++c) {
            sSD[warp][c][lane] = make_float2(pa[c] + pb[c], pa[c] - pb[c]);
            if (lane < 4)
                sSD[warp][c][32 + lane] =
                    make_float2(qa[c] + qb[c], qa[c] - qb[c]);
        }
        __syncwarp();

        // ---- prefetch next row ----
        prefetch();

        // ---- horizontal 5-tap pass into slot S5 (masked weights) ----
#pragma unroll
        for (int c = 0; c < C; ++c) {
            const u64* pSD = (const u64*)&sSD[warp][c][0];
            u64 ssd = 0ull, ssq = 0ull;
#pragma unroll
            for (int t = 0; t < 5; ++t) {
                const u64 pp = pSD[lane + t];
                ssd = fma2_(pp, wgm[t], ssd);
                ssq = fma2_(mul2_(pp, pp), wgm[t], ssq);
            }
            hSD[c][S5] = ssd;
            hSQ[c][S5] = ssq;
        }

        // ---- vertical 5-tap + epilogue for output row y0+s-4 ----
        if (s >= 4) {
            float num[C], den[C];
#pragma unroll
            for (int c = 0; c < C; ++c) {
                u64 vsd = 0ull, vsq = 0ull;
#pragma unroll
                for (int j = 0; j < 5; ++j) {
                    const int slot = (S5 + 1 + j) % 5;  // row s-4+j
                    vsd = fma2_(hSD[c][slot], wg[j], vsd);
                    vsq = fma2_(hSQ[c][slot], wg[j], vsq);
                }
                float cs, cd, css, csd;
                up2(vsd, cs, cd);     // conv(s), conv(d)
                up2(vsq, css, csd);   // conv(s^2), conv(d^2)
                const float cs2 = cs * cs, cd2 = cd * cd;
                const float m12 = (cs2 - cd2) * 0.25f;   // mu1*mu2
                const float msq = (cs2 + cd2) * 0.5f;    // mu1^2+mu2^2
                const float cab = (css - csd) * 0.25f;   // conv(ab)
                const float csum = (css + csd) * 0.5f;   // conv(a2)+conv(b2)
                const float s12  = cab - m12;            // sigma12
                const float svar = csum - msq;           // var1+var2
                num[c] = (2.0f * m12 + C1) * (2.0f * s12 + C2);
                den[c] = (msq + C1) * (svar + C2);
            }
            const float d01   = den[0] * den[1];
            const float denom = d01 * den[2];
            float numer = num[2] * d01;
            numer = fmaf(num[0], den[1] * den[2], numer);
            numer = fmaf(num[1], den[0] * den[2], numer);
            const int y = y0 + s - 4;
            out[(b * H + y) * W + xo] =
                __fdividef(numer, denom) * (1.0f / 3.0f);
        }
    };

    // ---- pipeline ----
    loadrow_c(y0 - 2);                               // row for step 0
    step(0, 0, [&] { loadrow_c(y0 - 1); });          // may be OOB (top)
    step(1, 1, [&] { loadrow_u(y0); });              // row y0 always valid

    for (int base = 2; base < 32; base += 5) {       // steady: s = 2..31
#pragma unroll
        for (int k = 0; k < 5; ++k) {
            // rows y0+1 .. y0+30: always valid -> unchecked loads
            step(base + k, (k + 2) % 5,
                 [&] { loadrow_u(y0 - 1 + base + k); });
        }
    }

    step(32, 2, [&] { loadrow_u(y0 + 31); });        // row y0+31 valid
    step(33, 3, [&] { loadrow_c(y0 + 32); });        // may be OOB (bottom)
    step(34, 4, [&] { loadrow_c(y0 + 33); });        // may be OOB (bottom)
    step(35, 0, [&] {});                             // last step, no prefetch
}

extern "C" void kernel_launch(void* const* d_in, const int* in_sizes, int n_in,
                              void* d_out, int out_size)
{
    const float* img1 = (const float*)d_in[0];
    const float* img2 = (const float*)d_in[1];
    const float* win  = (const float*)d_in[2];
    float* out = (float*)d_out;

    dim3 grid(W / BX, H / ROWS, NB);  // (4, 16, 16) = 1024 blocks
    ssim_kernel<<<grid, 128>>>(img1, img2, win, out);
}